// round 11
// baseline (speedup 1.0000x reference)
#include <cuda_runtime.h>
#include <cuda_bf16.h>

// RoiAlign: fm (1,256,50,50) f32, proposals (1024,4) f32 -> out (1024,256,7,7) f32
// Reference double-applies SCALE => /256 and clamps roi_w/h >= 1, so every sample
// coord lies in [0, 3.23]: all boxes read only fm[:, 0:5, 0:5]. Small-CTA design:
// 64 threads = 64 channels, grid (1024 boxes x 4 channel-quarters) = 4096 CTAs
// -> 12 CTAs/SM resident, phases of many independent CTAs interleave per SMSP.
// Per CTA: cooperative hot-patch fill -> per-channel patch in registers ->
// tx-first separable combine (each smem weight read once) -> staged coalesced
// float4 store. 3 block barriers total. Runtime-validated with a gmem fallback
// if the patch ever exceeds [0,4].

#define C_CH  256
#define HH    50
#define WW    50
#define OUTSZ 7
#define SSAMP 14    // OUT * SR
#define SPAN  5     // fixed patch 0..4 per axis
#define BTH   64    // threads = channels per CTA

__global__ __launch_bounds__(BTH, 12)
void roi_align_kernel(const float* __restrict__ fm,
                      const float* __restrict__ proposals,
                      float* __restrict__ out)
{
    const int tid = threadIdx.x;
    const int n   = blockIdx.x;      // box
    const int q   = blockIdx.y;      // channel quarter (0..3)

    // union buffer: first the hot patch (BTH*25), then the 49-float/ch stage.
    __shared__ __align__(16) float s_buf[BTH * 49];     // 12544 B
    __shared__ float s_h[2 * SSAMP], s_l[2 * SSAMP];
    __shared__ int   s_a0[2 * SSAMP], s_a1[2 * SSAMP];
    __shared__ float sWy[OUTSZ][SPAN], sWx[OUTSZ][SPAN];
    __shared__ int   s_ok;

    // ---------- cooperative fill of hot fm patch into s_buf[ch*25+k] ----------
    {
        const float* fmh = fm + (size_t)(q * BTH) * (HH * WW);
        #pragma unroll 1
        for (int j = 0; j < 25; j++) {
            int i = j * BTH + tid;           // 25*64 = 1600 exact
            int ch = i / 25, k = i % 25;
            s_buf[i] = fmh[ch * (HH * WW) + (k / 5) * WW + (k % 5)];
        }
    }

    // ---------- per-box axis sample params: 28 threads ----------
    if (tid < 2 * SSAMP) {
        const bool isY = tid < SSAMP;
        const int  s   = isY ? tid : tid - SSAMP;
        float4 p = reinterpret_cast<const float4*>(proposals)[n];
        const float sc = 0.0625f;
        float x1 = (p.x * sc) * sc, y1v = (p.y * sc) * sc;
        float x2 = (p.z * sc) * sc, y2v = (p.w * sc) * sc;
        float roiw = fmaxf(x2 - x1, 1.0f);
        float roih = fmaxf(y2v - y1v, 1.0f);
        float gg = ((float)s + 0.5f) * 0.5f;              // (s+0.5)/SR
        float v = isY ? (y1v + (roih * (1.0f / 7.0f)) * gg)
                      : (x1  + (roiw * (1.0f / 7.0f)) * gg);
        const int L = HH;                                  // H == W == 50
        bool valid = (v >= -1.0f) && (v <= (float)L);
        float vc = fminf(fmaxf(v, 0.0f), (float)(L - 1));
        int i0 = min((int)floorf(vc), L - 1);
        int i1 = min(i0 + 1, L - 1);
        float l = vc - (float)i0;
        float h = 1.0f - l;
        if (!valid) { h = 0.0f; l = 0.0f; }
        s_a0[tid] = i0; s_a1[tid] = i1; s_h[tid] = h; s_l[tid] = l;
    }
    __syncthreads();                                       // B1

    // ---------- preload channel patch to regs; build weights in parallel ----------
    float r[25];
    #pragma unroll
    for (int k = 0; k < 25; k++) r[k] = s_buf[tid * 25 + k];

    if (tid < 2 * OUTSZ) {                 // 14 threads build Wy / Wx
        const bool isY = tid < OUTSZ;
        const int  o   = isY ? tid : tid - OUTSZ;
        const int  off = isY ? 0 : SSAMP;
        float w[SPAN] = {0.f, 0.f, 0.f, 0.f, 0.f};
        #pragma unroll
        for (int k = 0; k < 2; k++) {
            int s = off + 2 * o + k;
            w[min(s_a0[s], SPAN - 1)] += 0.5f * s_h[s];
            w[min(s_a1[s], SPAN - 1)] += 0.5f * s_l[s];
        }
        #pragma unroll
        for (int p2 = 0; p2 < SPAN; p2++) {
            if (isY) sWy[o][p2] = w[p2]; else sWx[o][p2] = w[p2];
        }
    } else if (tid == 32) {
        int mx = -1;
        #pragma unroll
        for (int s = 0; s < 2 * SSAMP; s++) mx = max(mx, s_a1[s]);
        s_ok = (mx <= SPAN - 1) ? 1 : 0;
    }
    __syncthreads();                                       // B2

    const int c = q * BTH + tid;
    float* outb = out + (size_t)n * (C_CH * 49);

    if (s_ok) {
        // ---- phase 1 (regs only): tx[ox][y] = sum_x r[y][x] * Wx[ox][x] ----
        float tx[OUTSZ][SPAN];
        #pragma unroll
        for (int ox = 0; ox < OUTSZ; ox++) {
            float w0 = sWx[ox][0], w1 = sWx[ox][1], w2 = sWx[ox][2];
            float w3 = sWx[ox][3], w4 = sWx[ox][4];
            #pragma unroll
            for (int y = 0; y < SPAN; y++)
                tx[ox][y] = r[y*5+0]*w0 + r[y*5+1]*w1 + r[y*5+2]*w2
                          + r[y*5+3]*w3 + r[y*5+4]*w4;
        }

        // ---- phase 2: contract y, write straight to stage smem ----
        float* st = s_buf + tid * 49;
        #pragma unroll
        for (int oy = 0; oy < OUTSZ; oy++) {
            float wy0 = sWy[oy][0], wy1 = sWy[oy][1], wy2 = sWy[oy][2];
            float wy3 = sWy[oy][3], wy4 = sWy[oy][4];
            #pragma unroll
            for (int ox = 0; ox < OUTSZ; ox++)
                st[oy * 7 + ox] = tx[ox][0]*wy0 + tx[ox][1]*wy1 + tx[ox][2]*wy2
                                + tx[ox][3]*wy3 + tx[ox][4]*wy4;
        }
        __syncthreads();                                   // B3

        // ---- coalesced block store: 784 float4 = 12*64 + 16 ----
        float4* dst = reinterpret_cast<float4*>(outb + (size_t)q * (BTH * 49));
        const float4* src = reinterpret_cast<const float4*>(s_buf);
        #pragma unroll 4
        for (int it = 0; it < 12; it++)
            dst[it * BTH + tid] = src[it * BTH + tid];
        if (tid < 16)
            dst[12 * BTH + tid] = src[12 * BTH + tid];
    } else {
        // ---------- general fallback: direct gmem compute + store ----------
        const float* fmc = fm + (size_t)c * (HH * WW);
        float* outc = outb + (size_t)c * 49;
        for (int oy = 0; oy < OUTSZ; oy++) {
            for (int ox = 0; ox < OUTSZ; ox++) {
                float a = 0.0f;
                #pragma unroll
                for (int ky = 0; ky < 2; ky++) {
                    int sy = 2 * oy + ky;
                    int y0 = s_a0[sy] * WW, y1i = s_a1[sy] * WW;
                    float hy = s_h[sy], ly = s_l[sy];
                    #pragma unroll
                    for (int kx = 0; kx < 2; kx++) {
                        int sxi = SSAMP + 2 * ox + kx;
                        int x0 = s_a0[sxi], x1i = s_a1[sxi];
                        float hx = s_h[sxi], lx = s_l[sxi];
                        a += hy * (hx * fmc[y0 + x0]  + lx * fmc[y0 + x1i])
                           + ly * (hx * fmc[y1i + x0] + lx * fmc[y1i + x1i]);
                    }
                }
                outc[oy * 7 + ox] = a * 0.25f;
            }
        }
        __syncthreads();                                   // keep barrier uniform
    }
}

extern "C" void kernel_launch(void* const* d_in, const int* in_sizes, int n_in,
                              void* d_out, int out_size) {
    const float* fm    = (const float*)d_in[0];   // (1,256,50,50) f32
    const float* props = (const float*)d_in[1];   // (1024,4) f32
    float* out         = (float*)d_out;           // (1024,256,7,7) f32
    int N = in_sizes[1] / 4;
    dim3 grid(N, 4);
    roi_align_kernel<<<grid, BTH>>>(fm, props, out);
}

// round 13
// speedup vs baseline: 1.1909x; 1.1909x over previous
#include <cuda_runtime.h>
#include <cuda_bf16.h>

// RoiAlign: fm (1,256,50,50) f32, proposals (1024,4) f32 -> out (1024,256,7,7) f32
// Reference double-applies SCALE => /256 and clamps roi_w/h >= 1, so every sample
// coord lies in [0, 3.23]: all boxes read only fm[:, 0:5, 0:5]. R10 skeleton
// (hot-patch fill -> per-channel registers -> tx-first separable combine) but
// with WARP-AUTONOMOUS back half: after the 2 setup barriers, each warp stages
// its 32 channels into a private smem slice and copies it out with coalesced
// float4 stores, synchronized only by __syncwarp. Warps drift freely, so one
// warp's store burst overlaps another's FMA block. Runtime-validated per box
// with a gmem fallback if a patch ever exceeds [0,4].

#define C_CH  256
#define HH    50
#define WW    50
#define OUTSZ 7
#define SSAMP 14    // OUT * SR
#define SPAN  5     // fixed patch 0..4 per axis
#define BTH   128   // threads = channels per block-half
#define GBOX  2     // boxes per block
#define WSLICE (32 * 49)   // 1568 floats per warp slice

__global__ __launch_bounds__(BTH)
void roi_align_kernel(const float* __restrict__ fm,
                      const float* __restrict__ proposals,
                      float* __restrict__ out)
{
    const int tid  = threadIdx.x;
    const int wid  = tid >> 5;
    const int lane = tid & 31;
    const int half = blockIdx.y;
    const int n0   = blockIdx.x * GBOX;

    // union buffer: hot patch (BTH*25) during setup, then 4 warp-private
    // stage slices of 1568 floats each (4*1568 = BTH*49 exactly).
    __shared__ __align__(16) float s_buf[BTH * 49];     // 25088 B
    __shared__ float s_h[GBOX * 2 * SSAMP], s_l[GBOX * 2 * SSAMP];
    __shared__ int   s_a0[GBOX * 2 * SSAMP], s_a1[GBOX * 2 * SSAMP];
    __shared__ float sWy[GBOX][OUTSZ][SPAN], sWx[GBOX][OUTSZ][SPAN];
    __shared__ int   s_ok[GBOX];

    // ---------- cooperative fill of hot fm patch into s_buf[ch*25+k] ----------
    {
        const float* fmh = fm + (size_t)(half * BTH) * (HH * WW);
        #pragma unroll 1
        for (int j = 0; j < 25; j++) {
            int i = j * BTH + tid;
            int ch = i / 25, k = i % 25;
            s_buf[i] = fmh[ch * (HH * WW) + (k / 5) * WW + (k % 5)];
        }
    }

    // ---------- per-box axis sample params: GBOX*28 = 56 threads ----------
    if (tid < GBOX * 2 * SSAMP) {
        const int g = tid / (2 * SSAMP);
        const int j = tid % (2 * SSAMP);
        const bool isY = j < SSAMP;
        const int  s   = isY ? j : j - SSAMP;
        float4 p = reinterpret_cast<const float4*>(proposals)[n0 + g];
        const float sc = 0.0625f;
        float x1 = (p.x * sc) * sc, y1v = (p.y * sc) * sc;
        float x2 = (p.z * sc) * sc, y2v = (p.w * sc) * sc;
        float roiw = fmaxf(x2 - x1, 1.0f);
        float roih = fmaxf(y2v - y1v, 1.0f);
        float gg = ((float)s + 0.5f) * 0.5f;              // (s+0.5)/SR
        float v = isY ? (y1v + (roih * (1.0f / 7.0f)) * gg)
                      : (x1  + (roiw * (1.0f / 7.0f)) * gg);
        const int L = HH;                                  // H == W == 50
        bool valid = (v >= -1.0f) && (v <= (float)L);
        float vc = fminf(fmaxf(v, 0.0f), (float)(L - 1));
        int i0 = min((int)floorf(vc), L - 1);
        int i1 = min(i0 + 1, L - 1);
        float l = vc - (float)i0;
        float h = 1.0f - l;
        if (!valid) { h = 0.0f; l = 0.0f; }
        s_a0[tid] = i0; s_a1[tid] = i1; s_h[tid] = h; s_l[tid] = l;
    }
    __syncthreads();                                       // B1

    // ---------- preload channel patch to regs; build weights in parallel ----------
    float r[25];
    #pragma unroll
    for (int k = 0; k < 25; k++) r[k] = s_buf[tid * 25 + k];

    if (tid < GBOX * 2 * OUTSZ) {          // GBOX*14 = 28 threads
        const int g = tid / (2 * OUTSZ);
        const int j = tid % (2 * OUTSZ);
        const bool isY = j < OUTSZ;
        const int  o   = isY ? j : j - OUTSZ;
        const int  off = g * 2 * SSAMP + (isY ? 0 : SSAMP);
        float w[SPAN] = {0.f, 0.f, 0.f, 0.f, 0.f};
        #pragma unroll
        for (int k = 0; k < 2; k++) {
            int s = off + 2 * o + k;
            w[min(s_a0[s], SPAN - 1)] += 0.5f * s_h[s];
            w[min(s_a1[s], SPAN - 1)] += 0.5f * s_l[s];
        }
        #pragma unroll
        for (int q = 0; q < SPAN; q++) {
            if (isY) sWy[g][o][q] = w[q]; else sWx[g][o][q] = w[q];
        }
    } else if (tid >= 64 && tid < 64 + GBOX) {
        const int g = tid - 64;
        int mx = -1;
        #pragma unroll
        for (int s = 0; s < 2 * SSAMP; s++)
            mx = max(mx, s_a1[g * 2 * SSAMP + s]);
        s_ok[g] = (mx <= SPAN - 1) ? 1 : 0;
    }
    __syncthreads();                                       // B2 (last block barrier)

    const int c = half * BTH + tid;
    float* wslice = s_buf + wid * WSLICE;                  // warp-private stage

    #pragma unroll 1
    for (int g = 0; g < GBOX; g++) {
        float* outb = out + (size_t)(n0 + g) * (C_CH * 49);

        if (s_ok[g]) {
            // ---- phase 1 (regs only): tx[ox][y] = sum_x r[y][x] * Wx[ox][x] ----
            float tx[OUTSZ][SPAN];
            #pragma unroll
            for (int ox = 0; ox < OUTSZ; ox++) {
                float w0 = sWx[g][ox][0], w1 = sWx[g][ox][1], w2 = sWx[g][ox][2];
                float w3 = sWx[g][ox][3], w4 = sWx[g][ox][4];
                #pragma unroll
                for (int y = 0; y < SPAN; y++)
                    tx[ox][y] = r[y*5+0]*w0 + r[y*5+1]*w1 + r[y*5+2]*w2
                              + r[y*5+3]*w3 + r[y*5+4]*w4;
            }

            // ---- phase 2: contract y, stage into warp-private slice ----
            float* st = wslice + lane * 49;
            #pragma unroll
            for (int oy = 0; oy < OUTSZ; oy++) {
                float wy0 = sWy[g][oy][0], wy1 = sWy[g][oy][1], wy2 = sWy[g][oy][2];
                float wy3 = sWy[g][oy][3], wy4 = sWy[g][oy][4];
                #pragma unroll
                for (int ox = 0; ox < OUTSZ; ox++)
                    st[oy * 7 + ox] = tx[ox][0]*wy0 + tx[ox][1]*wy1 + tx[ox][2]*wy2
                                    + tx[ox][3]*wy3 + tx[ox][4]*wy4;
            }
            __syncwarp();

            // ---- warp-coalesced copy: 392 float4 = 12*32 + 8 ----
            float4* dst = reinterpret_cast<float4*>(outb)
                        + (size_t)half * (4 * 392) + (size_t)wid * 392;
            const float4* src = reinterpret_cast<const float4*>(wslice);
            #pragma unroll 4
            for (int it = 0; it < 12; it++)
                dst[it * 32 + lane] = src[it * 32 + lane];
            if (lane < 8)
                dst[12 * 32 + lane] = src[12 * 32 + lane];
            __syncwarp();   // copy reads done before next box's stage overwrite
        } else {
            // ---------- general fallback: direct gmem compute + store ----------
            const float* fmc = fm + (size_t)c * (HH * WW);
            float* outc = outb + (size_t)c * 49;
            const int off = g * 2 * SSAMP;
            for (int oy = 0; oy < OUTSZ; oy++) {
                for (int ox = 0; ox < OUTSZ; ox++) {
                    float a = 0.0f;
                    #pragma unroll
                    for (int ky = 0; ky < 2; ky++) {
                        int sy = off + 2 * oy + ky;
                        int y0 = s_a0[sy] * WW, y1i = s_a1[sy] * WW;
                        float hy = s_h[sy], ly = s_l[sy];
                        #pragma unroll
                        for (int kx = 0; kx < 2; kx++) {
                            int sxi = off + SSAMP + 2 * ox + kx;
                            int x0 = s_a0[sxi], x1i = s_a1[sxi];
                            float hx = s_h[sxi], lx = s_l[sxi];
                            a += hy * (hx * fmc[y0 + x0]  + lx * fmc[y0 + x1i])
                               + ly * (hx * fmc[y1i + x0] + lx * fmc[y1i + x1i]);
                        }
                    }
                    outc[oy * 7 + ox] = a * 0.25f;
                }
            }
        }
    }
}

extern "C" void kernel_launch(void* const* d_in, const int* in_sizes, int n_in,
                              void* d_out, int out_size) {
    const float* fm    = (const float*)d_in[0];   // (1,256,50,50) f32
    const float* props = (const float*)d_in[1];   // (1024,4) f32
    float* out         = (float*)d_out;           // (1024,256,7,7) f32
    int N = in_sizes[1] / 4;
    dim3 grid(N / GBOX, 2);
    roi_align_kernel<<<grid, BTH>>>(fm, props, out);
}